// round 3
// baseline (speedup 1.0000x reference)
#include <cuda_runtime.h>
#include <cuda_fp16.h>
#include <cstdint>

#define OUTF 2048
#define INF  2048
#define NNZV 262144
#define NN   65536

#define TM 128        // output tile (A rows)
#define TN 256        // node tile (B rows)
#define TK 32         // halves per K chunk
#define NSTAGE 3
#define NKSTEPS (INF / TK)   // 64

#define ROWH 40       // padded row stride in halves (80 bytes)
#define A_STAGE_B (TM * ROWH * 2)   // 10240
#define B_STAGE_B (TN * ROWH * 2)   // 20480
#define SMEM_BYTES (NSTAGE * (A_STAGE_B + B_STAGE_B))  // 92160

#define NSPLIT 4      // gemm split into 4 launches over n (also shifts ncu capture onto gemm)

// ---- scratch (device globals; no allocation allowed) ----
__device__ __align__(256) float  g_W32[OUTF * INF];          // 16 MB dense accumulator
__device__ __align__(256) __half g_W16[OUTF * INF];          // 8 MB fp16 W
__device__ __align__(256) __half g_Xh[(size_t)NN * INF];     // 256 MB fp16 x

// ---- helpers ----
__device__ __forceinline__ uint32_t smem_u32(const void* p) {
    return (uint32_t)__cvta_generic_to_shared(p);
}
__device__ __forceinline__ void cp16(uint32_t dst, const void* src) {
    asm volatile("cp.async.cg.shared.global [%0], [%1], 16;" :: "r"(dst), "l"(src) : "memory");
}
__device__ __forceinline__ void cp_commit() {
    asm volatile("cp.async.commit_group;" ::: "memory");
}
template <int N>
__device__ __forceinline__ void cp_wait() {
    asm volatile("cp.async.wait_group %0;" :: "n"(N) : "memory");
}
__device__ __forceinline__ void ldsm_x4(uint32_t& r0, uint32_t& r1, uint32_t& r2, uint32_t& r3,
                                        uint32_t addr) {
    asm volatile("ldmatrix.sync.aligned.m8n8.x4.shared.b16 {%0,%1,%2,%3}, [%4];"
                 : "=r"(r0), "=r"(r1), "=r"(r2), "=r"(r3) : "r"(addr));
}
__device__ __forceinline__ void mma16816(float* c, const uint32_t* a, uint32_t b0, uint32_t b1) {
    asm volatile(
        "mma.sync.aligned.m16n8k16.row.col.f32.f16.f16.f32 "
        "{%0,%1,%2,%3}, {%4,%5,%6,%7}, {%8,%9}, {%0,%1,%2,%3};"
        : "+f"(c[0]), "+f"(c[1]), "+f"(c[2]), "+f"(c[3])
        : "r"(a[0]), "r"(a[1]), "r"(a[2]), "r"(a[3]), "r"(b0), "r"(b1));
}

// ---- prologue kernels ----
__global__ void zero_w_kernel() {
    int i = blockIdx.x * blockDim.x + threadIdx.x;
    reinterpret_cast<float4*>(g_W32)[i] = make_float4(0.f, 0.f, 0.f, 0.f);
}
__global__ void scatter_kernel(const float* __restrict__ vals, const int* __restrict__ rows,
                               const int* __restrict__ cols) {
    int i = blockIdx.x * blockDim.x + threadIdx.x;
    atomicAdd(&g_W32[rows[i] * INF + cols[i]], vals[i]);
}
__global__ void conv_w_kernel() {
    int i = blockIdx.x * blockDim.x + threadIdx.x;  // per float4
    float4 v = reinterpret_cast<const float4*>(g_W32)[i];
    union { __half2 h[2]; uint2 u; } p;
    p.h[0] = __floats2half2_rn(v.x, v.y);
    p.h[1] = __floats2half2_rn(v.z, v.w);
    reinterpret_cast<uint2*>(g_W16)[i] = p.u;
}
__global__ void conv_x_kernel(const float* __restrict__ x) {
    size_t i = (size_t)blockIdx.x * blockDim.x + threadIdx.x;  // per float4
    float4 v = reinterpret_cast<const float4*>(x)[i];
    union { __half2 h[2]; uint2 u; } p;
    p.h[0] = __floats2half2_rn(v.x, v.y);
    p.h[1] = __floats2half2_rn(v.z, v.w);
    reinterpret_cast<uint2*>(g_Xh)[i] = p.u;
}

// ---- GEMM: out[n, o] = sum_k Xh[n,k] * W16[o,k] + bias[o] ----
// A = W rows (M=128 outputs), B = x rows (N=256 nodes), both K-major.
// 16 warps: warp tile 64x32 (wm in {0,1}, wn in 0..7) -> 4 warps/SMSP for latency hiding.
__global__ void __launch_bounds__(512, 1)
gemm_kernel(const float* __restrict__ bias, float* __restrict__ out, int n_tile_base) {
    extern __shared__ __align__(128) uint8_t smem[];
    uint8_t* sA = smem;                                  // NSTAGE * A_STAGE_B
    uint8_t* sB = smem + NSTAGE * A_STAGE_B;             // NSTAGE * B_STAGE_B

    const int tid = threadIdx.x;
    const int wid = tid >> 5;
    const int lid = tid & 31;
    const int wm = wid & 1;        // warp M index (2)
    const int wn = wid >> 1;       // warp N index (8)
    const int m0 = blockIdx.x * TM;
    const int n0 = (n_tile_base + blockIdx.y) * TN;

    const uint32_t sA_base = smem_u32(sA);
    const uint32_t sB_base = smem_u32(sB);

    // ---- async load of one stage (512 threads: A 1 chunk, B 2 chunks each) ----
    auto load_stage = [&](int stage, int kt) {
        const uint32_t a_dst = sA_base + stage * A_STAGE_B;
        const uint32_t b_dst = sB_base + stage * B_STAGE_B;
        const int kh = kt * TK;   // k offset in halves
        {
            int r = tid >> 2, kc = tid & 3;      // A: 512 chunks of 16B
            cp16(a_dst + r * (ROWH * 2) + kc * 16,
                 g_W16 + (size_t)(m0 + r) * INF + kh + kc * 8);
        }
#pragma unroll
        for (int i = 0; i < 2; i++) {            // B: 1024 chunks of 16B
            int c = tid + (i << 9);
            int r = c >> 2, kc = c & 3;
            cp16(b_dst + r * (ROWH * 2) + kc * 16,
                 g_Xh + (size_t)(n0 + r) * INF + kh + kc * 8);
        }
        cp_commit();
    };

    load_stage(0, 0);
    load_stage(1, 1);

    float acc[4][4][4];
#pragma unroll
    for (int mt = 0; mt < 4; mt++)
#pragma unroll
        for (int nt = 0; nt < 4; nt++)
#pragma unroll
            for (int e = 0; e < 4; e++) acc[mt][nt][e] = 0.f;

    // per-lane ldmatrix address components (in halves)
    const int a_row = lid & 15;                 // row within 16x16 tile
    const int a_koff = (lid >> 4) << 3;         // 0 or 8
    const int b_nrow = (lid & 7) + ((lid >> 4) << 3);   // n row within 16
    const int b_koff = ((lid >> 3) & 1) << 3;   // 0 or 8

    for (int kt = 0; kt < NKSTEPS; kt++) {
        const int stage = kt % NSTAGE;
        cp_wait<1>();          // stage kt complete (kt+1 may still be in flight)
        __syncthreads();
        if (kt + 2 < NKSTEPS) load_stage((kt + 2) % NSTAGE, kt + 2);

        const uint32_t aS = sA_base + stage * A_STAGE_B;
        const uint32_t bS = sB_base + stage * B_STAGE_B;

#pragma unroll
        for (int ks = 0; ks < 2; ks++) {        // two k16 steps per TK=32
            uint32_t af[4][4], bf[2][4];
#pragma unroll
            for (int mt = 0; mt < 4; mt++) {    // A: 64 rows
                uint32_t addr = aS + ((wm * 64 + mt * 16 + a_row) * ROWH + ks * 16 + a_koff) * 2;
                ldsm_x4(af[mt][0], af[mt][1], af[mt][2], af[mt][3], addr);
            }
#pragma unroll
            for (int j = 0; j < 2; j++) {       // B: 32 cols = 2 x n16
                uint32_t addr = bS + ((wn * 32 + j * 16 + b_nrow) * ROWH + ks * 16 + b_koff) * 2;
                ldsm_x4(bf[j][0], bf[j][1], bf[j][2], bf[j][3], addr);
            }
#pragma unroll
            for (int mt = 0; mt < 4; mt++)
#pragma unroll
                for (int j = 0; j < 2; j++) {
                    mma16816(acc[mt][2 * j],     af[mt], bf[j][0], bf[j][1]);
                    mma16816(acc[mt][2 * j + 1], af[mt], bf[j][2], bf[j][3]);
                }
        }
    }

    // ---- epilogue: out[n, o] += bias[o] ----
    const int q = lid >> 2;        // 0..7
    const int p2 = (lid & 3) << 1; // 0,2,4,6
#pragma unroll
    for (int mt = 0; mt < 4; mt++) {
        const int o_lo = m0 + wm * 64 + mt * 16 + q;
        const float bv_lo = bias[o_lo];
        const float bv_hi = bias[o_lo + 8];
#pragma unroll
        for (int nt = 0; nt < 4; nt++) {
            const int n = n0 + wn * 32 + nt * 8 + p2;
            float* o0 = out + (size_t)n * OUTF;
            float* o1 = out + (size_t)(n + 1) * OUTF;
            o0[o_lo]     = acc[mt][nt][0] + bv_lo;
            o1[o_lo]     = acc[mt][nt][1] + bv_lo;
            o0[o_lo + 8] = acc[mt][nt][2] + bv_hi;
            o1[o_lo + 8] = acc[mt][nt][3] + bv_hi;
        }
    }
}

extern "C" void kernel_launch(void* const* d_in, const int* in_sizes, int n_in,
                              void* d_out, int out_size) {
    (void)in_sizes; (void)n_in; (void)out_size;
    const float* x      = (const float*)d_in[0];
    const float* values = (const float*)d_in[1];
    const float* bias   = (const float*)d_in[2];
    const int*   rows   = (const int*)d_in[3];
    const int*   cols   = (const int*)d_in[4];
    float* out = (float*)d_out;

    zero_w_kernel<<<(OUTF * INF / 4) / 256, 256>>>();
    scatter_kernel<<<NNZV / 256, 256>>>(values, rows, cols);
    conv_w_kernel<<<(OUTF * INF / 4) / 256, 256>>>();
    conv_x_kernel<<<(int)(((size_t)NN * INF / 4) / 256), 256>>>(x);

    static bool attr_set = false;
    if (!attr_set) {
        cudaFuncSetAttribute(gemm_kernel, cudaFuncAttributeMaxDynamicSharedMemorySize, SMEM_BYTES);
        attr_set = true;
    }
    const int n_tiles_per_split = (NN / TN) / NSPLIT;   // 64
    for (int s = 0; s < NSPLIT; s++) {
        gemm_kernel<<<dim3(OUTF / TM, n_tiles_per_split), 512, SMEM_BYTES>>>(
            bias, out, s * n_tiles_per_split);
    }
}

// round 5
// speedup vs baseline: 1.2212x; 1.2212x over previous
#include <cuda_runtime.h>
#include <cuda_fp16.h>
#include <cstdint>

#define OUTF 2048
#define INF  2048
#define NNZV 262144
#define NN   65536

#define TM 128        // output tile (A rows)
#define TN 128        // node tile (B rows)
#define TK 64         // halves per K chunk
#define NSTAGE 2
#define NKSTEPS (INF / TK)   // 32

#define ROWH 72       // padded row stride in halves (144 B)
#define A_STAGE_B (TM * ROWH * 2)   // 18432
#define B_STAGE_B (TN * ROWH * 2)   // 18432
#define SMEM_BYTES (NSTAGE * (A_STAGE_B + B_STAGE_B))  // 73728 -> 2 CTAs/SM

#define NSPLIT 4      // gemm split into 4 launches over n (ncu capture targeting)

// ---- scratch (device globals; no allocation allowed) ----
__device__ __align__(256) float  g_W32[OUTF * INF];          // 16 MB dense accumulator
__device__ __align__(256) __half g_W16[OUTF * INF];          // 8 MB fp16 W
__device__ __align__(256) __half g_Xh[(size_t)NN * INF];     // 256 MB fp16 x

// ---- helpers ----
__device__ __forceinline__ uint32_t smem_u32(const void* p) {
    return (uint32_t)__cvta_generic_to_shared(p);
}
__device__ __forceinline__ void cp16(uint32_t dst, const void* src) {
    asm volatile("cp.async.cg.shared.global [%0], [%1], 16;" :: "r"(dst), "l"(src) : "memory");
}
__device__ __forceinline__ void cp_commit() {
    asm volatile("cp.async.commit_group;" ::: "memory");
}
template <int N>
__device__ __forceinline__ void cp_wait() {
    asm volatile("cp.async.wait_group %0;" :: "n"(N) : "memory");
}
__device__ __forceinline__ void ldsm_x4(uint32_t& r0, uint32_t& r1, uint32_t& r2, uint32_t& r3,
                                        uint32_t addr) {
    asm volatile("ldmatrix.sync.aligned.m8n8.x4.shared.b16 {%0,%1,%2,%3}, [%4];"
                 : "=r"(r0), "=r"(r1), "=r"(r2), "=r"(r3) : "r"(addr));
}
__device__ __forceinline__ void mma16816(float* c, const uint32_t* a, uint32_t b0, uint32_t b1) {
    asm volatile(
        "mma.sync.aligned.m16n8k16.row.col.f32.f16.f16.f32 "
        "{%0,%1,%2,%3}, {%4,%5,%6,%7}, {%8,%9}, {%0,%1,%2,%3};"
        : "+f"(c[0]), "+f"(c[1]), "+f"(c[2]), "+f"(c[3])
        : "r"(a[0]), "r"(a[1]), "r"(a[2]), "r"(a[3]), "r"(b0), "r"(b1));
}

// ---- prologue kernels ----
__global__ void zero_w_kernel() {
    int i = blockIdx.x * blockDim.x + threadIdx.x;
    reinterpret_cast<float4*>(g_W32)[i] = make_float4(0.f, 0.f, 0.f, 0.f);
}
__global__ void scatter_kernel(const float* __restrict__ vals, const int* __restrict__ rows,
                               const int* __restrict__ cols) {
    int i = blockIdx.x * blockDim.x + threadIdx.x;
    atomicAdd(&g_W32[rows[i] * INF + cols[i]], vals[i]);
}
__global__ void conv_w_kernel() {
    int i = blockIdx.x * blockDim.x + threadIdx.x;  // per float4
    float4 v = reinterpret_cast<const float4*>(g_W32)[i];
    union { __half2 h[2]; uint2 u; } p;
    p.h[0] = __floats2half2_rn(v.x, v.y);
    p.h[1] = __floats2half2_rn(v.z, v.w);
    reinterpret_cast<uint2*>(g_W16)[i] = p.u;
}
__global__ void conv_x_kernel(const float* __restrict__ x) {
    size_t i = (size_t)blockIdx.x * blockDim.x + threadIdx.x;  // per float4
    float4 v = reinterpret_cast<const float4*>(x)[i];
    union { __half2 h[2]; uint2 u; } p;
    p.h[0] = __floats2half2_rn(v.x, v.y);
    p.h[1] = __floats2half2_rn(v.z, v.w);
    reinterpret_cast<uint2*>(g_Xh)[i] = p.u;
}

// ---- GEMM: out[n, o] = sum_k Xh[n,k] * W16[o,k] + bias[o] ----
// A = W rows (M=128 outputs), B = x rows (N=128 nodes), K-major.
// 8 warps, warp tile 64x32. 2 CTAs co-resident per SM to fill barrier bubbles.
// Pipeline invariant: EVERY loop iteration commits exactly one cp.async group
// (real prefetch or empty), so cp_wait<1> at iter kt always covers group kt.
__global__ void __launch_bounds__(256, 2)
gemm_kernel(const float* __restrict__ bias, float* __restrict__ out, int n_tile_base) {
    extern __shared__ __align__(128) uint8_t smem[];
    uint8_t* sA = smem;                                  // NSTAGE * A_STAGE_B
    uint8_t* sB = smem + NSTAGE * A_STAGE_B;             // NSTAGE * B_STAGE_B

    const int tid = threadIdx.x;
    const int wid = tid >> 5;
    const int lid = tid & 31;
    const int wm = wid & 1;        // warp M index (2)
    const int wn = wid >> 1;       // warp N index (4)
    const int m0 = blockIdx.x * TM;
    const int n0 = (n_tile_base + blockIdx.y) * TN;

    const uint32_t sA_base = smem_u32(sA);
    const uint32_t sB_base = smem_u32(sB);

    // ---- async load of one stage: A,B each 128 rows x 128 B = 1024 chunks of 16B ----
    auto load_stage = [&](int stage, int kt) {
        const uint32_t a_dst = sA_base + stage * A_STAGE_B;
        const uint32_t b_dst = sB_base + stage * B_STAGE_B;
        const int kh = kt * TK;   // k offset in halves
#pragma unroll
        for (int i = 0; i < 4; i++) {
            int c = tid + (i << 8);
            int r = c >> 3, kc = c & 7;
            cp16(a_dst + r * (ROWH * 2) + kc * 16,
                 g_W16 + (size_t)(m0 + r) * INF + kh + kc * 8);
        }
#pragma unroll
        for (int i = 0; i < 4; i++) {
            int c = tid + (i << 8);
            int r = c >> 3, kc = c & 7;
            cp16(b_dst + r * (ROWH * 2) + kc * 16,
                 g_Xh + (size_t)(n0 + r) * INF + kh + kc * 8);
        }
        cp_commit();
    };

    load_stage(0, 0);
    load_stage(1, 1);

    float acc[4][4][4];
#pragma unroll
    for (int mt = 0; mt < 4; mt++)
#pragma unroll
        for (int nt = 0; nt < 4; nt++)
#pragma unroll
            for (int e = 0; e < 4; e++) acc[mt][nt][e] = 0.f;

    // per-lane ldmatrix address components (in halves)
    const int a_row = lid & 15;                 // row within 16x16 tile
    const int a_koff = (lid >> 4) << 3;         // 0 or 8
    const int b_nrow = (lid & 7) + ((lid >> 4) << 3);   // n row within 16
    const int b_koff = ((lid >> 3) & 1) << 3;   // 0 or 8

    for (int kt = 0; kt < NKSTEPS; kt++) {
        const int stage = kt & 1;
        // Committed so far: G0..G_{kt+1} (each prior iter committed exactly one
        // group, real or empty). <=1 pending => G_kt resident. Sound at tail.
        cp_wait<1>();
        __syncthreads();

        const uint32_t aS = sA_base + stage * A_STAGE_B;
        const uint32_t bS = sB_base + stage * B_STAGE_B;

#pragma unroll
        for (int ks = 0; ks < 4; ks++) {        // four k16 steps per TK=64
            uint32_t af[4][4], bf[2][4];
#pragma unroll
            for (int mt = 0; mt < 4; mt++) {    // A: 64 rows
                uint32_t addr = aS + ((wm * 64 + mt * 16 + a_row) * ROWH + ks * 16 + a_koff) * 2;
                ldsm_x4(af[mt][0], af[mt][1], af[mt][2], af[mt][3], addr);
            }
#pragma unroll
            for (int j = 0; j < 2; j++) {       // B: 32 cols = 2 x n16
                uint32_t addr = bS + ((wn * 32 + j * 16 + b_nrow) * ROWH + ks * 16 + b_koff) * 2;
                ldsm_x4(bf[j][0], bf[j][1], bf[j][2], bf[j][3], addr);
            }
#pragma unroll
            for (int mt = 0; mt < 4; mt++)
#pragma unroll
                for (int j = 0; j < 2; j++) {
                    mma16816(acc[mt][2 * j],     af[mt], bf[j][0], bf[j][1]);
                    mma16816(acc[mt][2 * j + 1], af[mt], bf[j][2], bf[j][3]);
                }
        }

        __syncthreads();       // all warps done reading this stage
        if (kt + 2 < NKSTEPS) load_stage(stage, kt + 2);
        else                  cp_commit();       // empty group keeps wait-count sound
    }

    // ---- epilogue: out[n, o] += bias[o] ----
    const int q = lid >> 2;        // 0..7
    const int p2 = (lid & 3) << 1; // 0,2,4,6
#pragma unroll
    for (int mt = 0; mt < 4; mt++) {
        const int o_lo = m0 + wm * 64 + mt * 16 + q;
        const float bv_lo = bias[o_lo];
        const float bv_hi = bias[o_lo + 8];
#pragma unroll
        for (int nt = 0; nt < 4; nt++) {
            const int n = n0 + wn * 32 + nt * 8 + p2;
            float* o0 = out + (size_t)n * OUTF;
            float* o1 = out + (size_t)(n + 1) * OUTF;
            o0[o_lo]     = acc[mt][nt][0] + bv_lo;
            o1[o_lo]     = acc[mt][nt][1] + bv_lo;
            o0[o_lo + 8] = acc[mt][nt][2] + bv_hi;
            o1[o_lo + 8] = acc[mt][nt][3] + bv_hi;
        }
    }
}

extern "C" void kernel_launch(void* const* d_in, const int* in_sizes, int n_in,
                              void* d_out, int out_size) {
    (void)in_sizes; (void)n_in; (void)out_size;
    const float* x      = (const float*)d_in[0];
    const float* values = (const float*)d_in[1];
    const float* bias   = (const float*)d_in[2];
    const int*   rows   = (const int*)d_in[3];
    const int*   cols   = (const int*)d_in[4];
    float* out = (float*)d_out;

    zero_w_kernel<<<(OUTF * INF / 4) / 256, 256>>>();
    scatter_kernel<<<NNZV / 256, 256>>>(values, rows, cols);
    conv_w_kernel<<<(OUTF * INF / 4) / 256, 256>>>();
    conv_x_kernel<<<(int)(((size_t)NN * INF / 4) / 256), 256>>>(x);

    static bool attr_set = false;
    if (!attr_set) {
        cudaFuncSetAttribute(gemm_kernel, cudaFuncAttributeMaxDynamicSharedMemorySize, SMEM_BYTES);
        attr_set = true;
    }
    const int n_tiles_per_split = (NN / TN) / NSPLIT;   // 128
    for (int s = 0; s < NSPLIT; s++) {
        gemm_kernel<<<dim3(OUTF / TM, n_tiles_per_split), 256, SMEM_BYTES>>>(
            bias, out, s * n_tiles_per_split);
    }
}

// round 6
// speedup vs baseline: 1.2275x; 1.0051x over previous
#include <cuda_runtime.h>
#include <cuda_fp16.h>
#include <cstdint>

#define OUTF 2048
#define INF  2048
#define NNZV 262144
#define NN   65536

#define TM 128        // output tile (A rows)
#define TN 128        // node tile (B rows)
#define TK 64         // halves per K chunk
#define NSTAGE 3
#define NKSTEPS (INF / TK)   // 32

#define ROWH 72       // padded row stride in halves (144 B, 16B-aligned rows, conflict-free ldmatrix)
#define A_STAGE_B (TM * ROWH * 2)   // 18432
#define B_STAGE_B (TN * ROWH * 2)   // 18432
#define SMEM_BYTES (NSTAGE * (A_STAGE_B + B_STAGE_B))  // 110592 -> 2 CTAs/SM (221KB/228KB)

#define NSPLIT 4      // gemm split into 4 launches over n (ncu capture targeting)

// ---- scratch (device globals; no allocation allowed) ----
__device__ __align__(256) float  g_W32[OUTF * INF];          // 16 MB dense accumulator
__device__ __align__(256) __half g_W16[OUTF * INF];          // 8 MB fp16 W
__device__ __align__(256) __half g_Xh[(size_t)NN * INF];     // 256 MB fp16 x

// ---- helpers ----
__device__ __forceinline__ uint32_t smem_u32(const void* p) {
    return (uint32_t)__cvta_generic_to_shared(p);
}
__device__ __forceinline__ void cp16(uint32_t dst, const void* src) {
    asm volatile("cp.async.cg.shared.global [%0], [%1], 16;" :: "r"(dst), "l"(src) : "memory");
}
__device__ __forceinline__ void cp_commit() {
    asm volatile("cp.async.commit_group;" ::: "memory");
}
template <int N>
__device__ __forceinline__ void cp_wait() {
    asm volatile("cp.async.wait_group %0;" :: "n"(N) : "memory");
}
__device__ __forceinline__ void ldsm_x4(uint32_t& r0, uint32_t& r1, uint32_t& r2, uint32_t& r3,
                                        uint32_t addr) {
    asm volatile("ldmatrix.sync.aligned.m8n8.x4.shared.b16 {%0,%1,%2,%3}, [%4];"
                 : "=r"(r0), "=r"(r1), "=r"(r2), "=r"(r3) : "r"(addr));
}
__device__ __forceinline__ void mma16816(float* c, const uint32_t* a, uint32_t b0, uint32_t b1) {
    asm volatile(
        "mma.sync.aligned.m16n8k16.row.col.f32.f16.f16.f32 "
        "{%0,%1,%2,%3}, {%4,%5,%6,%7}, {%8,%9}, {%0,%1,%2,%3};"
        : "+f"(c[0]), "+f"(c[1]), "+f"(c[2]), "+f"(c[3])
        : "r"(a[0]), "r"(a[1]), "r"(a[2]), "r"(a[3]), "r"(b0), "r"(b1));
}

// ---- prologue kernels ----
__global__ void zero_w_kernel() {
    int i = blockIdx.x * blockDim.x + threadIdx.x;
    reinterpret_cast<float4*>(g_W32)[i] = make_float4(0.f, 0.f, 0.f, 0.f);
}
__global__ void scatter_kernel(const float* __restrict__ vals, const int* __restrict__ rows,
                               const int* __restrict__ cols) {
    int i = blockIdx.x * blockDim.x + threadIdx.x;
    atomicAdd(&g_W32[rows[i] * INF + cols[i]], vals[i]);
}
__global__ void conv_w_kernel() {
    int i = blockIdx.x * blockDim.x + threadIdx.x;  // per float4
    float4 v = reinterpret_cast<const float4*>(g_W32)[i];
    union { __half2 h[2]; uint2 u; } p;
    p.h[0] = __floats2half2_rn(v.x, v.y);
    p.h[1] = __floats2half2_rn(v.z, v.w);
    reinterpret_cast<uint2*>(g_W16)[i] = p.u;
}
__global__ void conv_x_kernel(const float* __restrict__ x) {
    size_t i = (size_t)blockIdx.x * blockDim.x + threadIdx.x;  // per float4
    float4 v = reinterpret_cast<const float4*>(x)[i];
    union { __half2 h[2]; uint2 u; } p;
    p.h[0] = __floats2half2_rn(v.x, v.y);
    p.h[1] = __floats2half2_rn(v.z, v.w);
    reinterpret_cast<uint2*>(g_Xh)[i] = p.u;
}

// ---- GEMM: out[n, o] = sum_k Xh[n,k] * W16[o,k] + bias[o] ----
// A = W rows (M=128 outputs), B = x rows (N=128 nodes), K-major.
// 8 warps (warp tile 64x32), 2 CTAs/SM, 3-stage cp.async pipeline with ONE
// __syncthreads per k-iter: load for kt+2 goes into buffer (kt-1)%3, whose
// readers finished before this iteration's top barrier.
// Commit invariant: every iteration commits exactly one group (real or empty),
// so cp_wait<1> at iter kt always guarantees group kt is resident.
__global__ void __launch_bounds__(256, 2)
gemm_kernel(const float* __restrict__ bias, float* __restrict__ out, int n_tile_base) {
    extern __shared__ __align__(128) uint8_t smem[];
    uint8_t* sA = smem;                                  // NSTAGE * A_STAGE_B
    uint8_t* sB = smem + NSTAGE * A_STAGE_B;             // NSTAGE * B_STAGE_B

    const int tid = threadIdx.x;
    const int wid = tid >> 5;
    const int lid = tid & 31;
    const int wm = wid & 1;        // warp M index (2)
    const int wn = wid >> 1;       // warp N index (4)
    const int m0 = blockIdx.x * TM;
    const int n0 = (n_tile_base + blockIdx.y) * TN;

    const uint32_t sA_base = smem_u32(sA);
    const uint32_t sB_base = smem_u32(sB);

    // ---- async load of one stage: A,B each 128 rows x 128 B = 1024 chunks of 16B ----
    auto load_stage = [&](int stage, int kt) {
        const uint32_t a_dst = sA_base + stage * A_STAGE_B;
        const uint32_t b_dst = sB_base + stage * B_STAGE_B;
        const int kh = kt * TK;   // k offset in halves
#pragma unroll
        for (int i = 0; i < 4; i++) {
            int c = tid + (i << 8);
            int r = c >> 3, kc = c & 7;
            cp16(a_dst + r * (ROWH * 2) + kc * 16,
                 g_W16 + (size_t)(m0 + r) * INF + kh + kc * 8);
        }
#pragma unroll
        for (int i = 0; i < 4; i++) {
            int c = tid + (i << 8);
            int r = c >> 3, kc = c & 7;
            cp16(b_dst + r * (ROWH * 2) + kc * 16,
                 g_Xh + (size_t)(n0 + r) * INF + kh + kc * 8);
        }
        cp_commit();
    };

    load_stage(0, 0);
    load_stage(1, 1);

    float acc[4][4][4];
#pragma unroll
    for (int mt = 0; mt < 4; mt++)
#pragma unroll
        for (int nt = 0; nt < 4; nt++)
#pragma unroll
            for (int e = 0; e < 4; e++) acc[mt][nt][e] = 0.f;

    // per-lane ldmatrix address components (in halves)
    const int a_row = lid & 15;                 // row within 16x16 tile
    const int a_koff = (lid >> 4) << 3;         // 0 or 8
    const int b_nrow = (lid & 7) + ((lid >> 4) << 3);   // n row within 16
    const int b_koff = ((lid >> 3) & 1) << 3;   // 0 or 8

    int stage = 0;
    for (int kt = 0; kt < NKSTEPS; kt++) {
        // Pending groups <= 1 after this (G_{kt+1}); G_kt is resident.
        cp_wait<1>();
        __syncthreads();   // also proves: all warps finished reading buffer (kt-1)%3

        // Prefetch kt+2 into buffer (kt+2)%3 == (kt-1)%3 BEFORE compute.
        if (kt + 2 < NKSTEPS) {
            int pstage = stage + 2; if (pstage >= NSTAGE) pstage -= NSTAGE;
            load_stage(pstage, kt + 2);
        } else {
            cp_commit();   // empty group keeps wait-count sound at the tail
        }

        const uint32_t aS = sA_base + stage * A_STAGE_B;
        const uint32_t bS = sB_base + stage * B_STAGE_B;

#pragma unroll
        for (int ks = 0; ks < 4; ks++) {        // four k16 steps per TK=64
            uint32_t af[4][4], bf[2][4];
#pragma unroll
            for (int mt = 0; mt < 4; mt++) {    // A: 64 rows
                uint32_t addr = aS + ((wm * 64 + mt * 16 + a_row) * ROWH + ks * 16 + a_koff) * 2;
                ldsm_x4(af[mt][0], af[mt][1], af[mt][2], af[mt][3], addr);
            }
#pragma unroll
            for (int j = 0; j < 2; j++) {       // B: 32 cols = 2 x n16
                uint32_t addr = bS + ((wn * 32 + j * 16 + b_nrow) * ROWH + ks * 16 + b_koff) * 2;
                ldsm_x4(bf[j][0], bf[j][1], bf[j][2], bf[j][3], addr);
            }
#pragma unroll
            for (int mt = 0; mt < 4; mt++)
#pragma unroll
                for (int j = 0; j < 2; j++) {
                    mma16816(acc[mt][2 * j],     af[mt], bf[j][0], bf[j][1]);
                    mma16816(acc[mt][2 * j + 1], af[mt], bf[j][2], bf[j][3]);
                }
        }

        if (++stage >= NSTAGE) stage = 0;
    }

    // ---- epilogue: out[n, o] += bias[o] ----
    const int q = lid >> 2;        // 0..7
    const int p2 = (lid & 3) << 1; // 0,2,4,6
#pragma unroll
    for (int mt = 0; mt < 4; mt++) {
        const int o_lo = m0 + wm * 64 + mt * 16 + q;
        const float bv_lo = bias[o_lo];
        const float bv_hi = bias[o_lo + 8];
#pragma unroll
        for (int nt = 0; nt < 4; nt++) {
            const int n = n0 + wn * 32 + nt * 8 + p2;
            float* o0 = out + (size_t)n * OUTF;
            float* o1 = out + (size_t)(n + 1) * OUTF;
            o0[o_lo]     = acc[mt][nt][0] + bv_lo;
            o1[o_lo]     = acc[mt][nt][1] + bv_lo;
            o0[o_lo + 8] = acc[mt][nt][2] + bv_hi;
            o1[o_lo + 8] = acc[mt][nt][3] + bv_hi;
        }
    }
}

extern "C" void kernel_launch(void* const* d_in, const int* in_sizes, int n_in,
                              void* d_out, int out_size) {
    (void)in_sizes; (void)n_in; (void)out_size;
    const float* x      = (const float*)d_in[0];
    const float* values = (const float*)d_in[1];
    const float* bias   = (const float*)d_in[2];
    const int*   rows   = (const int*)d_in[3];
    const int*   cols   = (const int*)d_in[4];
    float* out = (float*)d_out;

    zero_w_kernel<<<(OUTF * INF / 4) / 256, 256>>>();
    scatter_kernel<<<NNZV / 256, 256>>>(values, rows, cols);
    conv_w_kernel<<<(OUTF * INF / 4) / 256, 256>>>();
    conv_x_kernel<<<(int)(((size_t)NN * INF / 4) / 256), 256>>>(x);

    static bool attr_set = false;
    if (!attr_set) {
        cudaFuncSetAttribute(gemm_kernel, cudaFuncAttributeMaxDynamicSharedMemorySize, SMEM_BYTES);
        attr_set = true;
    }
    const int n_tiles_per_split = (NN / TN) / NSPLIT;   // 128
    for (int s = 0; s < NSPLIT; s++) {
        gemm_kernel<<<dim3(OUTF / TM, n_tiles_per_split), 256, SMEM_BYTES>>>(
            bias, out, s * n_tiles_per_split);
    }
}